// round 15
// baseline (speedup 1.0000x reference)
#include <cuda_runtime.h>
#include <cuda_bf16.h>
#include <cstdint>
#include <cstddef>
#include <cfloat>

// ---------------------------------------------------------------------------
// Sbox16: out = c + sum_seg M[:, seg*256 + argmax_seg(x@W1^T + b1)]
//   M = W3@W2 (128x4096), c = W3@b2 + b3
// R15: R14 + s1 candidate enqueue via ballot-aggregated global atomics
//      (removes sync3 and the serial tid0 flush -> 3 barriers/iter).
// ---------------------------------------------------------------------------

static constexpr int BMAX = 32768;
static constexpr int D    = 128;
static constexpr int H    = 4096;
static constexpr int NSEG = 16;
static constexpr float TAU = 0.13f;
static constexpr int NTILE = BMAX / 64;      // 512 row tiles
static constexpr int SGRID = 37;             // CTAs per segment (2 waves @ occ2)
static constexpr int QCAP  = 1 << 20;

__device__ __nv_bfloat16 g_xb [BMAX * D];
__device__ __nv_bfloat16 g_w1b[H * D];
__device__ __nv_bfloat16 g_w2t[2 * (size_t)H * H];
__device__ __nv_bfloat16 g_w3b[2 * H * D];
__device__ float g_mpart[8 * H * D];
__device__ float g_MT [H * D];
__device__ float g_c  [D];
__device__ int   g_idx[BMAX * NSEG];
__device__ unsigned long long g_kb[BMAX * NSEG];
__device__ uint32_t g_q[QCAP];
__device__ int g_qcnt;

// ------------------------------- ptx helpers -------------------------------
__device__ __forceinline__ uint32_t smem_u32(const void* p) {
    uint32_t a;
    asm("{ .reg .u64 t; cvta.to.shared.u64 t, %1; cvt.u32.u64 %0, t; }" : "=r"(a) : "l"(p));
    return a;
}
__device__ __forceinline__ void ldsm_x4(uint32_t* r, uint32_t addr) {
    asm volatile("ldmatrix.sync.aligned.m8n8.x4.shared.b16 {%0,%1,%2,%3}, [%4];"
                 : "=r"(r[0]), "=r"(r[1]), "=r"(r[2]), "=r"(r[3]) : "r"(addr));
}
__device__ __forceinline__ void mma_bf16(float* d, const uint32_t* a,
                                         uint32_t b0, uint32_t b1) {
    asm volatile("mma.sync.aligned.m16n8k16.row.col.f32.bf16.bf16.f32 "
                 "{%0,%1,%2,%3}, {%4,%5,%6,%7}, {%8,%9}, {%0,%1,%2,%3};"
                 : "+f"(d[0]), "+f"(d[1]), "+f"(d[2]), "+f"(d[3])
                 : "r"(a[0]), "r"(a[1]), "r"(a[2]), "r"(a[3]), "r"(b0), "r"(b1));
}
__device__ __forceinline__ uint32_t ford(float f) {
    uint32_t u = __float_as_uint(f);
    return (u & 0x80000000u) ? ~u : (u | 0x80000000u);
}
__device__ __forceinline__ float iford(uint32_t u) {
    uint32_t v = (u & 0x80000000u) ? (u & 0x7FFFFFFFu) : ~u;
    return __uint_as_float(v);
}
__device__ __forceinline__ void cpasync16(uint32_t dst, const void* src) {
    asm volatile("cp.async.cg.shared.global [%0], [%1], 16;" :: "r"(dst), "l"(src));
}
#define CP_COMMIT() asm volatile("cp.async.commit_group;" ::: "memory")
#define CP_WAIT1()  asm volatile("cp.async.wait_group 1;" ::: "memory")

// ------------------------------ prepasses ----------------------------------
__global__ __launch_bounds__(256) void convertb_kernel(const float* __restrict__ src,
                                                       __nv_bfloat16* __restrict__ dst,
                                                       int n8) {
    int i = blockIdx.x * 256 + threadIdx.x;
    if (i >= n8) return;
    const float4* s4 = (const float4*)src;
    float4 a = s4[i * 2], b = s4[i * 2 + 1];
    __nv_bfloat162 p0 = __float22bfloat162_rn(make_float2(a.x, a.y));
    __nv_bfloat162 p1 = __float22bfloat162_rn(make_float2(a.z, a.w));
    __nv_bfloat162 p2 = __float22bfloat162_rn(make_float2(b.x, b.y));
    __nv_bfloat162 p3 = __float22bfloat162_rn(make_float2(b.z, b.w));
    uint4 o;
    o.x = *(uint32_t*)&p0; o.y = *(uint32_t*)&p1;
    o.z = *(uint32_t*)&p2; o.w = *(uint32_t*)&p3;
    ((uint4*)dst)[i] = o;
}

__global__ __launch_bounds__(256) void w3split_kernel(const float* __restrict__ W3) {
    int i = blockIdx.x * 256 + threadIdx.x;
    if (i >= H * D / 2) return;
    float2 v = ((const float2*)W3)[i];
    __nv_bfloat16 a0 = __float2bfloat16(v.x);
    __nv_bfloat16 b0 = __float2bfloat16(v.x - __bfloat162float(a0));
    __nv_bfloat16 a1 = __float2bfloat16(v.y);
    __nv_bfloat16 b1 = __float2bfloat16(v.y - __bfloat162float(a1));
    __nv_bfloat162 pa = {a0, a1}, pb = {b0, b1};
    ((__nv_bfloat162*)g_w3b)[i] = pa;
    ((__nv_bfloat162*)g_w3b)[H * D / 2 + i] = pb;
}

__global__ __launch_bounds__(256) void w2split_kernel(const float* __restrict__ W2) {
    __shared__ float tile[64][68];
    const int tid = threadIdx.x;
    const int j0 = blockIdx.x * 64;
    const int k0 = blockIdx.y * 64;
    #pragma unroll
    for (int p = 0; p < 4; p++) {
        int q = tid + p * 256;
        int r = q >> 4, c = (q & 15) * 4;
        *(float4*)&tile[r][c] = *(const float4*)&W2[(size_t)(j0 + r) * H + k0 + c];
    }
    __syncthreads();
    #pragma unroll
    for (int p = 0; p < 2; p++) {
        int q = tid + p * 256;
        int k = q >> 3, cs = (q & 7) * 8;
        __nv_bfloat16 ma[8], mb[8];
        #pragma unroll
        for (int e = 0; e < 8; e++) {
            float v = tile[cs + e][k];
            ma[e] = __float2bfloat16(v);
            mb[e] = __float2bfloat16(v - __bfloat162float(ma[e]));
        }
        size_t off = (size_t)(k0 + k) * H + j0 + cs;
        *(uint4*)(g_w2t + off) = *(uint4*)ma;
        *(uint4*)(g_w2t + (size_t)H * H + off) = *(uint4*)mb;
    }
}

// ---------------------------------- c ------------------------------------
__global__ __launch_bounds__(256) void c_kernel(const float* __restrict__ W3,
                                                const float* __restrict__ b2,
                                                const float* __restrict__ b3) {
    const int lane = threadIdx.x & 31;
    const int i = (blockIdx.x * 256 + threadIdx.x) >> 5;   // 0..127
    const float4* row = (const float4*)(W3 + (size_t)i * H);
    const float4* bb  = (const float4*)b2;
    float s = 0.f;
    #pragma unroll
    for (int k = 0; k < 32; k++) {
        float4 a = __ldg(&row[lane + k * 32]);
        float4 b = __ldg(&bb[lane + k * 32]);
        s += a.x * b.x + a.y * b.y + a.z * b.z + a.w * b.w;
    }
    #pragma unroll
    for (int off = 16; off > 0; off >>= 1)
        s += __shfl_xor_sync(0xffffffffu, s, off);
    if (lane == 0) g_c[i] = s + b3[i];
}

// ----------------- M via mma.sync: MT[k][i] = sum_j W2[j][k]W3[i][j] --------
static constexpr int MM_SMEM = 65536;

__global__ __launch_bounds__(256, 2) void mm2_kernel() {
    extern __shared__ char sm[];
    const int tid  = threadIdx.x;
    const int lane = tid & 31;
    const int wid  = tid >> 5;
    const int wr   = wid >> 2;
    const int wc   = wid & 3;
    const int k0   = blockIdx.x * 128;
    const int j0   = blockIdx.y * 512;

    const uint32_t sA = smem_u32(sm);
    const uint32_t sB = sA + 32768;

    float acc[4][4][4];
    #pragma unroll
    for (int mt = 0; mt < 4; mt++)
        #pragma unroll
        for (int nt = 0; nt < 4; nt++)
            #pragma unroll
            for (int e = 0; e < 4; e++) acc[mt][nt][e] = 0.f;

    for (int jc = 0; jc < 8; jc++) {
        __syncthreads();
        #pragma unroll
        for (int t = 0; t < 2; t++) {
            const __nv_bfloat16* srcA = g_w2t + (size_t)t * H * H
                                      + (size_t)k0 * H + j0 + jc * 64;
            #pragma unroll
            for (int i = 0; i < 4; i++) {
                int q = tid + i * 256;
                int r = q >> 3, c = q & 7;
                *(uint4*)(sm + t * 16384 + r * 128 + (((c ^ (r & 7)) & 7) << 4)) =
                    *(const uint4*)(srcA + (size_t)r * H + c * 8);
            }
        }
        #pragma unroll
        for (int t = 0; t < 2; t++) {
            const __nv_bfloat16* srcB = g_w3b + (size_t)t * H * D
                                      + j0 + jc * 64;
            #pragma unroll
            for (int i = 0; i < 4; i++) {
                int q = tid + i * 256;
                int r = q >> 3, c = q & 7;
                *(uint4*)(sm + 32768 + t * 16384 + r * 128 + (((c ^ (r & 7)) & 7) << 4)) =
                    *(const uint4*)(srcB + (size_t)r * H + c * 8);
            }
        }
        __syncthreads();

        #pragma unroll
        for (int ks = 0; ks < 4; ks++) {
            uint32_t b0[2][4], b1[2][4], a[4][4];
            #pragma unroll
            for (int g = 0; g < 2; g++) {
                int r = wc * 32 + g * 16 + (lane & 7) + ((lane >> 4) << 3);
                int c = ks * 2 + ((lane >> 3) & 1);
                uint32_t sw = (uint32_t)((c ^ (r & 7)) & 7) << 4;
                ldsm_x4(b0[g], sB + r * 128 + sw);
                ldsm_x4(b1[g], sB + 16384 + r * 128 + sw);
            }
            #pragma unroll
            for (int mt = 0; mt < 4; mt++) {
                int r = wr * 64 + mt * 16 + (lane & 15);
                int c = ks * 2 + (lane >> 4);
                ldsm_x4(a[mt], sA + r * 128 + ((uint32_t)((c ^ (r & 7)) & 7) << 4));
            }
            #pragma unroll
            for (int mt = 0; mt < 4; mt++)
                #pragma unroll
                for (int n8 = 0; n8 < 4; n8++) {
                    mma_bf16(acc[mt][n8], a[mt], b0[n8 >> 1][(n8 & 1) * 2],
                             b0[n8 >> 1][(n8 & 1) * 2 + 1]);
                    mma_bf16(acc[mt][n8], a[mt], b1[n8 >> 1][(n8 & 1) * 2],
                             b1[n8 >> 1][(n8 & 1) * 2 + 1]);
                }
            #pragma unroll
            for (int mt = 0; mt < 4; mt++) {
                int r = wr * 64 + mt * 16 + (lane & 15);
                int c = ks * 2 + (lane >> 4);
                ldsm_x4(a[mt], sA + 16384 + r * 128 + ((uint32_t)((c ^ (r & 7)) & 7) << 4));
            }
            #pragma unroll
            for (int mt = 0; mt < 4; mt++)
                #pragma unroll
                for (int n8 = 0; n8 < 4; n8++)
                    mma_bf16(acc[mt][n8], a[mt], b0[n8 >> 1][(n8 & 1) * 2],
                             b0[n8 >> 1][(n8 & 1) * 2 + 1]);
        }
    }

    float* dst = g_mpart + (size_t)blockIdx.y * (H * D) + (size_t)k0 * 128;
    #pragma unroll
    for (int mt = 0; mt < 4; mt++)
        #pragma unroll
        for (int n8 = 0; n8 < 4; n8++)
            #pragma unroll
            for (int h = 0; h < 2; h++) {
                int r  = wr * 64 + mt * 16 + h * 8 + (lane >> 2);
                int cs = wc * 32 + n8 * 8 + (lane & 3) * 2;
                *(float2*)&dst[(size_t)r * 128 + cs] =
                    make_float2(acc[mt][n8][h * 2], acc[mt][n8][h * 2 + 1]);
            }
}

__global__ __launch_bounds__(256) void mreduce_kernel() {
    int i = blockIdx.x * 256 + threadIdx.x;
    if (i >= H * D / 4) return;
    float4 s = make_float4(0.f, 0.f, 0.f, 0.f);
    #pragma unroll
    for (int p = 0; p < 8; p++) {
        float4 v = ((const float4*)(g_mpart + (size_t)p * H * D))[i];
        s.x += v.x; s.y += v.y; s.z += v.z; s.w += v.w;
    }
    ((float4*)g_MT)[i] = s;
}

// ------------------ stage-1 persistent GEMM + top-2 epilogue ----------------
// R11 shape; 3 barriers/iter; ballot-aggregated global enqueue.
static constexpr int OFF_B    = 0;         // 65536
static constexpr int OFF_A    = 65536;     // 2 x 16384 -> 98304
static constexpr int OFF_BS   = 98304;     // 1024
static constexpr int OFF_RKEY = 99328;     // u64[64][4] = 2048
static constexpr int OFF_RV2  = 101376;    // f32[64][4] = 1024
static constexpr int OFF_RMF  = 102400;    // f32[64]    = 256
static constexpr int OFF_FLAG = 102656;    // int[64]    = 256
static constexpr int S1_SMEM  = 102912;

__global__ __launch_bounds__(256, 2) void s1mma_kernel(const float* __restrict__ x,
                                                       const float* __restrict__ W1,
                                                       const float* __restrict__ b1) {
    extern __shared__ char sm[];
    const int tid  = threadIdx.x;
    const int lane = tid & 31;
    const int wid  = tid >> 5;
    const int wr   = wid >> 2;
    const int wc   = wid & 3;
    const int seg  = blockIdx.y;

    float* bs  = (float*)(sm + OFF_BS);
    unsigned long long (*rkey)[4] = (unsigned long long(*)[4])(sm + OFF_RKEY);
    float (*rv2)[4] = (float(*)[4])(sm + OFF_RV2);
    float* rmf = (float*)(sm + OFF_RMF);
    int* flag  = (int*)(sm + OFF_FLAG);

    const uint32_t sBase = smem_u32(sm);
    const uint32_t sB = sBase + OFF_B;
    const uint32_t sA = sBase + OFF_A;

    bs[tid] = b1[seg * 256 + tid];

    const uint4* wb4 = (const uint4*)g_w1b + (size_t)seg * 256 * 16;
    #pragma unroll
    for (int i = 0; i < 16; i++) {
        int qq = tid + i * 256;
        int r = qq >> 4, c = qq & 15;
        *(uint4*)(sm + OFF_B + r * 256 + ((c ^ (r & 7)) << 4)) = wb4[r * 16 + c];
    }

    {
        const uint4* src = (const uint4*)g_xb + (size_t)blockIdx.x * 64 * 16;
        #pragma unroll
        for (int i = 0; i < 4; i++) {
            int qq = tid + i * 256;
            int r = qq >> 4, c = qq & 15;
            cpasync16(sA + r * 256 + ((c ^ (r & 7)) << 4), src + r * 16 + c);
        }
    }
    CP_COMMIT();

    int it = 0;
    for (int t = blockIdx.x; t < NTILE; t += SGRID, it++) {
        int tn = t + SGRID;
        if (tn < NTILE) {
            uint32_t dbuf = sA + ((it + 1) & 1) * 16384;
            const uint4* src = (const uint4*)g_xb + (size_t)tn * 64 * 16;
            #pragma unroll
            for (int i = 0; i < 4; i++) {
                int qq = tid + i * 256;
                int r = qq >> 4, c = qq & 15;
                cpasync16(dbuf + r * 256 + ((c ^ (r & 7)) << 4), src + r * 16 + c);
            }
        }
        CP_COMMIT();
        CP_WAIT1();
        __syncthreads();                               // sync0

        const uint32_t sAc = sA + (it & 1) * 16384;

        float acc[2][8][4];
        #pragma unroll
        for (int mt = 0; mt < 2; mt++)
            #pragma unroll
            for (int nt = 0; nt < 8; nt++)
                #pragma unroll
                for (int e = 0; e < 4; e++) acc[mt][nt][e] = 0.f;

        #pragma unroll
        for (int ks = 0; ks < 8; ks++) {
            uint32_t a[2][4], b[4][4];
            #pragma unroll
            for (int mt = 0; mt < 2; mt++) {
                int r = wr * 32 + mt * 16 + (lane & 15);
                int c = ks * 2 + (lane >> 4);
                ldsm_x4(a[mt], sAc + r * 256 + ((uint32_t)(c ^ (r & 7)) << 4));
            }
            #pragma unroll
            for (int g = 0; g < 4; g++) {
                int r = wc * 64 + g * 16 + (lane & 7) + ((lane >> 4) << 3);
                int c = ks * 2 + ((lane >> 3) & 1);
                ldsm_x4(b[g], sB + r * 256 + ((uint32_t)(c ^ (r & 7)) << 4));
            }
            #pragma unroll
            for (int mt = 0; mt < 2; mt++)
                #pragma unroll
                for (int n8 = 0; n8 < 8; n8++)
                    mma_bf16(acc[mt][n8], a[mt], b[n8 >> 1][(n8 & 1) * 2],
                             b[n8 >> 1][(n8 & 1) * 2 + 1]);
        }

        const int q  = lane >> 2;
        const int qt = lane & 3;

        // bias pre-add (once)
        #pragma unroll
        for (int nt = 0; nt < 8; nt++) {
            float b0v = bs[wc * 64 + nt * 8 + qt * 2];
            float b1v = bs[wc * 64 + nt * 8 + qt * 2 + 1];
            #pragma unroll
            for (int mt = 0; mt < 2; mt++) {
                acc[mt][nt][0] += b0v; acc[mt][nt][1] += b1v;
                acc[mt][nt][2] += b0v; acc[mt][nt][3] += b1v;
            }
        }

        // register top-2 per row per quadrant: max-tree + masked second-max
        #pragma unroll
        for (int mt = 0; mt < 2; mt++)
            #pragma unroll
            for (int h = 0; h < 2; h++) {
                float m = -FLT_MAX;
                #pragma unroll
                for (int nt = 0; nt < 8; nt++) {
                    m = fmaxf(m, acc[mt][nt][h * 2]);
                    m = fmaxf(m, acc[mt][nt][h * 2 + 1]);
                }
                int i1 = 0;
                #pragma unroll
                for (int j = 15; j >= 0; j--) {
                    int nt = j >> 1, c2 = j & 1;
                    int cs = wc * 64 + nt * 8 + qt * 2 + c2;
                    if (acc[mt][nt][h * 2 + c2] == m) i1 = cs;
                }
                float v2 = -FLT_MAX;
                #pragma unroll
                for (int j = 0; j < 16; j++) {
                    int nt = j >> 1, c2 = j & 1;
                    int cs = wc * 64 + nt * 8 + qt * 2 + c2;
                    float v = (cs == i1) ? -FLT_MAX : acc[mt][nt][h * 2 + c2];
                    v2 = fmaxf(v2, v);
                }
                float v1 = m;
                #pragma unroll
                for (int off = 1; off <= 2; off <<= 1) {
                    float ov1 = __shfl_xor_sync(0xffffffffu, v1, off);
                    int   oi1 = __shfl_xor_sync(0xffffffffu, i1, off);
                    float ov2 = __shfl_xor_sync(0xffffffffu, v2, off);
                    bool owin = (ov1 > v1) || (ov1 == v1 && oi1 < i1);
                    if (owin) { v2 = fmaxf(v1, ov2); v1 = ov1; i1 = oi1; }
                    else      { v2 = fmaxf(v2, ov1); }
                }
                if (qt == 0) {
                    int rl = wr * 32 + mt * 16 + h * 8 + q;
                    rkey[rl][wc] =
                        ((unsigned long long)ford(v1) << 32) | (uint32_t)(255 - i1);
                    rv2[rl][wc] = v2;
                }
            }
        __syncthreads();                               // sync1

        // merge quadrants, classify, direct-write unambiguous
        if (tid < 64) {
            unsigned long long K = rkey[tid][0];
            #pragma unroll
            for (int q2 = 1; q2 < 4; q2++) {
                unsigned long long kq = rkey[tid][q2];
                if (kq > K) K = kq;
            }
            float v1 = iford((uint32_t)(K >> 32));
            float s2 = -FLT_MAX;
            #pragma unroll
            for (int q2 = 0; q2 < 4; q2++) {
                unsigned long long kq = rkey[tid][q2];
                float cv = (kq == K) ? rv2[tid][q2] : iford((uint32_t)(kq >> 32));
                s2 = fmaxf(s2, cv);
            }
            int fl = (v1 - s2 <= TAU) ? 1 : 0;
            flag[tid] = fl;
            size_t pair = (size_t)(t * 64 + tid) * NSEG + seg;
            if (!fl) {
                g_idx[pair] = 255 - (int)(K & 0xFFu);
            } else {
                rmf[tid] = v1;
                g_kb[pair] = 0ull;
            }
        }
        __syncthreads();                               // sync2

        // candidate enqueue (ambiguous rows only), ballot-aggregated
        #pragma unroll
        for (int mt = 0; mt < 2; mt++)
            #pragma unroll
            for (int h = 0; h < 2; h++) {
                int rl = wr * 32 + mt * 16 + h * 8 + q;
                bool fl = flag[rl] != 0;
                float thr = rmf[rl] - TAU;   // stale ok when !fl
                uint32_t ecode = ((uint32_t)(t * 64 + rl) << 12) | ((uint32_t)seg << 8);
                #pragma unroll
                for (int nt = 0; nt < 8; nt++)
                    #pragma unroll
                    for (int c2 = 0; c2 < 2; c2++) {
                        float v = acc[mt][nt][h * 2 + c2];
                        bool p = fl && (v >= thr);
                        unsigned mask = __ballot_sync(0xffffffffu, p);
                        if (mask) {
                            int n = __popc(mask);
                            int leader = __ffs(mask) - 1;
                            int base = 0;
                            if (lane == leader) base = atomicAdd(&g_qcnt, n);
                            base = __shfl_sync(0xffffffffu, base, leader);
                            if (p) {
                                int rank = __popc(mask & ((1u << lane) - 1u));
                                int pos = base + rank;
                                if (pos < QCAP)
                                    g_q[pos] = ecode |
                                        (uint32_t)(wc * 64 + nt * 8 + qt * 2 + c2);
                            }
                        }
                    }
            }
    }
}

// ------------------------- rescore + finalize -------------------------------
__global__ __launch_bounds__(256) void rescore_kernel(const float* __restrict__ x,
                                                      const float* __restrict__ W1,
                                                      const float* __restrict__ b1) {
    const int lane = threadIdx.x & 31;
    const int gw = (blockIdx.x * 256 + threadIdx.x) >> 5;
    const int nw = gridDim.x * 8;
    int n = g_qcnt;
    if (n > QCAP) n = QCAP;
    for (int i = gw; i < n; i += nw) {
        uint32_t e = g_q[i];
        int row = e >> 12, seg = (e >> 8) & 15, col = e & 255;
        const float4* xr = (const float4*)(x  + (size_t)row * 128);
        const float4* wv = (const float4*)(W1 + (size_t)(seg * 256 + col) * 128);
        float4 xa = __ldg(&xr[lane]);
        float4 wa = __ldg(&wv[lane]);
        float s = xa.x * wa.x + xa.y * wa.y + xa.z * wa.z + xa.w * wa.w;
        #pragma unroll
        for (int off = 16; off > 0; off >>= 1)
            s += __shfl_xor_sync(0xffffffffu, s, off);
        if (lane == 0) {
            float val = s + __ldg(&b1[seg * 256 + col]);
            unsigned long long key =
                ((unsigned long long)ford(val) << 32) | (uint32_t)(255 - col);
            atomicMax(&g_kb[(size_t)row * NSEG + seg], key);
        }
    }
}

__global__ __launch_bounds__(256) void finalize_kernel() {
    int n = g_qcnt;
    if (n > QCAP) n = QCAP;
    for (int i = blockIdx.x * 256 + threadIdx.x; i < n; i += gridDim.x * 256) {
        uint32_t e = g_q[i];
        size_t pair = (size_t)(e >> 12) * NSEG + ((e >> 8) & 15);
        g_idx[pair] = 255 - (int)(g_kb[pair] & 0xFFu);
    }
}

// --------------------------------- gather ---------------------------------
__global__ __launch_bounds__(128) void gather_kernel(float* __restrict__ out) {
    const int rowbase = blockIdx.x * 16;
    const int t = threadIdx.x;
    __shared__ int sidx[16][16];
    #pragma unroll
    for (int qq = t; qq < 256; qq += 128)
        sidx[qq >> 4][qq & 15] = g_idx[(size_t)(rowbase + (qq >> 4)) * NSEG + (qq & 15)];
    __syncthreads();

    const float cv = g_c[t];
    float acc[16];
    #pragma unroll
    for (int r = 0; r < 16; r++) acc[r] = cv;

    #pragma unroll
    for (int s = 0; s < NSEG; s++) {
        #pragma unroll
        for (int r = 0; r < 16; r++) {
            int col = (s << 8) + sidx[r][s];
            acc[r] += g_MT[(size_t)col * D + t];
        }
    }
    #pragma unroll
    for (int r = 0; r < 16; r++)
        out[(size_t)(rowbase + r) * D + t] = acc[r];
}

// ------------------------------- launcher ----------------------------------
extern "C" void kernel_launch(void* const* d_in, const int* in_sizes, int n_in,
                              void* d_out, int out_size) {
    const float* x  = (const float*)d_in[0];
    const float* W1 = (const float*)d_in[1];
    const float* b1 = (const float*)d_in[2];
    const float* W2 = (const float*)d_in[3];
    const float* b2 = (const float*)d_in[4];
    const float* W3 = (const float*)d_in[5];
    const float* b3 = (const float*)d_in[6];
    float* out = (float*)d_out;
    const int B = in_sizes[0] / D;   // 32768

    void *p_xb = nullptr, *p_w1b = nullptr, *p_qcnt = nullptr;
    cudaGetSymbolAddress(&p_xb,  g_xb);
    cudaGetSymbolAddress(&p_w1b, g_w1b);
    cudaGetSymbolAddress(&p_qcnt, g_qcnt);

    cudaFuncSetAttribute(s1mma_kernel,
                         cudaFuncAttributeMaxDynamicSharedMemorySize, S1_SMEM);
    cudaFuncSetAttribute(mm2_kernel,
                         cudaFuncAttributeMaxDynamicSharedMemorySize, MM_SMEM);

    static cudaStream_t s2 = nullptr;
    static cudaEvent_t evF = nullptr, evJ = nullptr;
    if (s2 == nullptr) {
        cudaStreamCreateWithFlags(&s2, cudaStreamNonBlocking);
        cudaEventCreateWithFlags(&evF, cudaEventDisableTiming);
        cudaEventCreateWithFlags(&evJ, cudaEventDisableTiming);
    }

    cudaMemsetAsync(p_qcnt, 0, sizeof(int));

    // fork the weight-only M-path onto s2
    cudaEventRecord(evF, 0);
    cudaStreamWaitEvent(s2, evF, 0);
    w3split_kernel<<<(H * D / 2 + 255) / 256, 256, 0, s2>>>(W3);
    w2split_kernel<<<dim3(H / 64, H / 64), 256, 0, s2>>>(W2);
    c_kernel<<<16, 256, 0, s2>>>(W3, b2, b3);
    mm2_kernel<<<dim3(32, 8), 256, MM_SMEM, s2>>>();
    mreduce_kernel<<<(H * D / 4 + 255) / 256, 256, 0, s2>>>();
    cudaEventRecord(evJ, s2);

    // main chain: x/W1 bf16 convert -> s1 -> rescore -> finalize
    convertb_kernel<<<(B * D / 8 + 255) / 256, 256>>>(x,  (__nv_bfloat16*)p_xb,  B * D / 8);
    convertb_kernel<<<(H * D / 8 + 255) / 256, 256>>>(W1, (__nv_bfloat16*)p_w1b, H * D / 8);
    s1mma_kernel<<<dim3(SGRID, NSEG), 256, S1_SMEM>>>(x, W1, b1);
    rescore_kernel<<<2048, 256>>>(x, W1, b1);
    finalize_kernel<<<512, 256>>>();

    // join M-path, then gather
    cudaStreamWaitEvent(0, evJ, 0);
    gather_kernel<<<B / 16, 128>>>(out);
}

// round 16
// speedup vs baseline: 1.2799x; 1.2799x over previous
#include <cuda_runtime.h>
#include <cuda_bf16.h>
#include <cstdint>
#include <cstddef>
#include <cfloat>

// ---------------------------------------------------------------------------
// Sbox16: out = c + sum_seg M[:, seg*256 + argmax_seg(x@W1^T + b1)]
//   M = W3@W2 (128x4096), c = W3@b2 + b3
// R16: R14 base (stream-forked M-path, R11 s1 semantics) with s1 widened to
//      512 threads (warps 2r x 8c, warp tile 32x32, acc 32 regs) -> 32
//      warps/SM at occ 2 for latency hiding.
// ---------------------------------------------------------------------------

static constexpr int BMAX = 32768;
static constexpr int D    = 128;
static constexpr int H    = 4096;
static constexpr int NSEG = 16;
static constexpr float TAU = 0.13f;
static constexpr int NTILE = BMAX / 64;      // 512 row tiles
static constexpr int SGRID = 37;             // CTAs per segment (2 waves @ occ2)
static constexpr int QCAP  = 1 << 20;

__device__ __nv_bfloat16 g_xb [BMAX * D];
__device__ __nv_bfloat16 g_w1b[H * D];
__device__ __nv_bfloat16 g_w2t[2 * (size_t)H * H];
__device__ __nv_bfloat16 g_w3b[2 * H * D];
__device__ float g_mpart[8 * H * D];
__device__ float g_MT [H * D];
__device__ float g_c  [D];
__device__ int   g_idx[BMAX * NSEG];
__device__ unsigned long long g_kb[BMAX * NSEG];
__device__ uint32_t g_q[QCAP];
__device__ int g_qcnt;

// ------------------------------- ptx helpers -------------------------------
__device__ __forceinline__ uint32_t smem_u32(const void* p) {
    uint32_t a;
    asm("{ .reg .u64 t; cvta.to.shared.u64 t, %1; cvt.u32.u64 %0, t; }" : "=r"(a) : "l"(p));
    return a;
}
__device__ __forceinline__ void ldsm_x4(uint32_t* r, uint32_t addr) {
    asm volatile("ldmatrix.sync.aligned.m8n8.x4.shared.b16 {%0,%1,%2,%3}, [%4];"
                 : "=r"(r[0]), "=r"(r[1]), "=r"(r[2]), "=r"(r[3]) : "r"(addr));
}
__device__ __forceinline__ void mma_bf16(float* d, const uint32_t* a,
                                         uint32_t b0, uint32_t b1) {
    asm volatile("mma.sync.aligned.m16n8k16.row.col.f32.bf16.bf16.f32 "
                 "{%0,%1,%2,%3}, {%4,%5,%6,%7}, {%8,%9}, {%0,%1,%2,%3};"
                 : "+f"(d[0]), "+f"(d[1]), "+f"(d[2]), "+f"(d[3])
                 : "r"(a[0]), "r"(a[1]), "r"(a[2]), "r"(a[3]), "r"(b0), "r"(b1));
}
__device__ __forceinline__ uint32_t ford(float f) {
    uint32_t u = __float_as_uint(f);
    return (u & 0x80000000u) ? ~u : (u | 0x80000000u);
}
__device__ __forceinline__ float iford(uint32_t u) {
    uint32_t v = (u & 0x80000000u) ? (u & 0x7FFFFFFFu) : ~u;
    return __uint_as_float(v);
}
__device__ __forceinline__ void cpasync16(uint32_t dst, const void* src) {
    asm volatile("cp.async.cg.shared.global [%0], [%1], 16;" :: "r"(dst), "l"(src));
}
#define CP_COMMIT() asm volatile("cp.async.commit_group;" ::: "memory")
#define CP_WAIT1()  asm volatile("cp.async.wait_group 1;" ::: "memory")

// ------------------------------ prepasses ----------------------------------
__global__ __launch_bounds__(256) void convertb_kernel(const float* __restrict__ src,
                                                       __nv_bfloat16* __restrict__ dst,
                                                       int n8) {
    int i = blockIdx.x * 256 + threadIdx.x;
    if (i >= n8) return;
    const float4* s4 = (const float4*)src;
    float4 a = s4[i * 2], b = s4[i * 2 + 1];
    __nv_bfloat162 p0 = __float22bfloat162_rn(make_float2(a.x, a.y));
    __nv_bfloat162 p1 = __float22bfloat162_rn(make_float2(a.z, a.w));
    __nv_bfloat162 p2 = __float22bfloat162_rn(make_float2(b.x, b.y));
    __nv_bfloat162 p3 = __float22bfloat162_rn(make_float2(b.z, b.w));
    uint4 o;
    o.x = *(uint32_t*)&p0; o.y = *(uint32_t*)&p1;
    o.z = *(uint32_t*)&p2; o.w = *(uint32_t*)&p3;
    ((uint4*)dst)[i] = o;
}

__global__ __launch_bounds__(256) void w3split_kernel(const float* __restrict__ W3) {
    int i = blockIdx.x * 256 + threadIdx.x;
    if (i >= H * D / 2) return;
    float2 v = ((const float2*)W3)[i];
    __nv_bfloat16 a0 = __float2bfloat16(v.x);
    __nv_bfloat16 b0 = __float2bfloat16(v.x - __bfloat162float(a0));
    __nv_bfloat16 a1 = __float2bfloat16(v.y);
    __nv_bfloat16 b1 = __float2bfloat16(v.y - __bfloat162float(a1));
    __nv_bfloat162 pa = {a0, a1}, pb = {b0, b1};
    ((__nv_bfloat162*)g_w3b)[i] = pa;
    ((__nv_bfloat162*)g_w3b)[H * D / 2 + i] = pb;
}

__global__ __launch_bounds__(256) void w2split_kernel(const float* __restrict__ W2) {
    __shared__ float tile[64][68];
    const int tid = threadIdx.x;
    const int j0 = blockIdx.x * 64;
    const int k0 = blockIdx.y * 64;
    #pragma unroll
    for (int p = 0; p < 4; p++) {
        int q = tid + p * 256;
        int r = q >> 4, c = (q & 15) * 4;
        *(float4*)&tile[r][c] = *(const float4*)&W2[(size_t)(j0 + r) * H + k0 + c];
    }
    __syncthreads();
    #pragma unroll
    for (int p = 0; p < 2; p++) {
        int q = tid + p * 256;
        int k = q >> 3, cs = (q & 7) * 8;
        __nv_bfloat16 ma[8], mb[8];
        #pragma unroll
        for (int e = 0; e < 8; e++) {
            float v = tile[cs + e][k];
            ma[e] = __float2bfloat16(v);
            mb[e] = __float2bfloat16(v - __bfloat162float(ma[e]));
        }
        size_t off = (size_t)(k0 + k) * H + j0 + cs;
        *(uint4*)(g_w2t + off) = *(uint4*)ma;
        *(uint4*)(g_w2t + (size_t)H * H + off) = *(uint4*)mb;
    }
}

// ---------------------------------- c ------------------------------------
__global__ __launch_bounds__(256) void c_kernel(const float* __restrict__ W3,
                                                const float* __restrict__ b2,
                                                const float* __restrict__ b3) {
    const int lane = threadIdx.x & 31;
    const int i = (blockIdx.x * 256 + threadIdx.x) >> 5;   // 0..127
    const float4* row = (const float4*)(W3 + (size_t)i * H);
    const float4* bb  = (const float4*)b2;
    float s = 0.f;
    #pragma unroll
    for (int k = 0; k < 32; k++) {
        float4 a = __ldg(&row[lane + k * 32]);
        float4 b = __ldg(&bb[lane + k * 32]);
        s += a.x * b.x + a.y * b.y + a.z * b.z + a.w * b.w;
    }
    #pragma unroll
    for (int off = 16; off > 0; off >>= 1)
        s += __shfl_xor_sync(0xffffffffu, s, off);
    if (lane == 0) g_c[i] = s + b3[i];
}

// ----------------- M via mma.sync: MT[k][i] = sum_j W2[j][k]W3[i][j] --------
static constexpr int MM_SMEM = 65536;

__global__ __launch_bounds__(256, 2) void mm2_kernel() {
    extern __shared__ char sm[];
    const int tid  = threadIdx.x;
    const int lane = tid & 31;
    const int wid  = tid >> 5;
    const int wr   = wid >> 2;
    const int wc   = wid & 3;
    const int k0   = blockIdx.x * 128;
    const int j0   = blockIdx.y * 512;

    const uint32_t sA = smem_u32(sm);
    const uint32_t sB = sA + 32768;

    float acc[4][4][4];
    #pragma unroll
    for (int mt = 0; mt < 4; mt++)
        #pragma unroll
        for (int nt = 0; nt < 4; nt++)
            #pragma unroll
            for (int e = 0; e < 4; e++) acc[mt][nt][e] = 0.f;

    for (int jc = 0; jc < 8; jc++) {
        __syncthreads();
        #pragma unroll
        for (int t = 0; t < 2; t++) {
            const __nv_bfloat16* srcA = g_w2t + (size_t)t * H * H
                                      + (size_t)k0 * H + j0 + jc * 64;
            #pragma unroll
            for (int i = 0; i < 4; i++) {
                int q = tid + i * 256;
                int r = q >> 3, c = q & 7;
                *(uint4*)(sm + t * 16384 + r * 128 + (((c ^ (r & 7)) & 7) << 4)) =
                    *(const uint4*)(srcA + (size_t)r * H + c * 8);
            }
        }
        #pragma unroll
        for (int t = 0; t < 2; t++) {
            const __nv_bfloat16* srcB = g_w3b + (size_t)t * H * D
                                      + j0 + jc * 64;
            #pragma unroll
            for (int i = 0; i < 4; i++) {
                int q = tid + i * 256;
                int r = q >> 3, c = q & 7;
                *(uint4*)(sm + 32768 + t * 16384 + r * 128 + (((c ^ (r & 7)) & 7) << 4)) =
                    *(const uint4*)(srcB + (size_t)r * H + c * 8);
            }
        }
        __syncthreads();

        #pragma unroll
        for (int ks = 0; ks < 4; ks++) {
            uint32_t b0[2][4], b1[2][4], a[4][4];
            #pragma unroll
            for (int g = 0; g < 2; g++) {
                int r = wc * 32 + g * 16 + (lane & 7) + ((lane >> 4) << 3);
                int c = ks * 2 + ((lane >> 3) & 1);
                uint32_t sw = (uint32_t)((c ^ (r & 7)) & 7) << 4;
                ldsm_x4(b0[g], sB + r * 128 + sw);
                ldsm_x4(b1[g], sB + 16384 + r * 128 + sw);
            }
            #pragma unroll
            for (int mt = 0; mt < 4; mt++) {
                int r = wr * 64 + mt * 16 + (lane & 15);
                int c = ks * 2 + (lane >> 4);
                ldsm_x4(a[mt], sA + r * 128 + ((uint32_t)((c ^ (r & 7)) & 7) << 4));
            }
            #pragma unroll
            for (int mt = 0; mt < 4; mt++)
                #pragma unroll
                for (int n8 = 0; n8 < 4; n8++) {
                    mma_bf16(acc[mt][n8], a[mt], b0[n8 >> 1][(n8 & 1) * 2],
                             b0[n8 >> 1][(n8 & 1) * 2 + 1]);
                    mma_bf16(acc[mt][n8], a[mt], b1[n8 >> 1][(n8 & 1) * 2],
                             b1[n8 >> 1][(n8 & 1) * 2 + 1]);
                }
            #pragma unroll
            for (int mt = 0; mt < 4; mt++) {
                int r = wr * 64 + mt * 16 + (lane & 15);
                int c = ks * 2 + (lane >> 4);
                ldsm_x4(a[mt], sA + 16384 + r * 128 + ((uint32_t)((c ^ (r & 7)) & 7) << 4));
            }
            #pragma unroll
            for (int mt = 0; mt < 4; mt++)
                #pragma unroll
                for (int n8 = 0; n8 < 4; n8++)
                    mma_bf16(acc[mt][n8], a[mt], b0[n8 >> 1][(n8 & 1) * 2],
                             b0[n8 >> 1][(n8 & 1) * 2 + 1]);
        }
    }

    float* dst = g_mpart + (size_t)blockIdx.y * (H * D) + (size_t)k0 * 128;
    #pragma unroll
    for (int mt = 0; mt < 4; mt++)
        #pragma unroll
        for (int n8 = 0; n8 < 4; n8++)
            #pragma unroll
            for (int h = 0; h < 2; h++) {
                int r  = wr * 64 + mt * 16 + h * 8 + (lane >> 2);
                int cs = wc * 32 + n8 * 8 + (lane & 3) * 2;
                *(float2*)&dst[(size_t)r * 128 + cs] =
                    make_float2(acc[mt][n8][h * 2], acc[mt][n8][h * 2 + 1]);
            }
}

__global__ __launch_bounds__(256) void mreduce_kernel() {
    int i = blockIdx.x * 256 + threadIdx.x;
    if (i >= H * D / 4) return;
    float4 s = make_float4(0.f, 0.f, 0.f, 0.f);
    #pragma unroll
    for (int p = 0; p < 8; p++) {
        float4 v = ((const float4*)(g_mpart + (size_t)p * H * D))[i];
        s.x += v.x; s.y += v.y; s.z += v.z; s.w += v.w;
    }
    ((float4*)g_MT)[i] = s;
}

// ------------------ stage-1 persistent GEMM + top-2 epilogue ----------------
// 512 threads, warps 2r x 8c, warp tile 32x32, acc 32 regs. occ 2 -> 32
// warps/SM. Same semantics as R14 (smem list + tid0 flush, 4 barriers/iter).
static constexpr int LIST_CAP = 512;
static constexpr int OFF_B    = 0;         // 65536
static constexpr int OFF_A    = 65536;     // 2 x 16384 -> 98304
static constexpr int OFF_BS   = 98304;     // 1024
static constexpr int OFF_RKEY = 99328;     // u64[64][8] = 4096
static constexpr int OFF_RV2  = 103424;    // f32[64][8] = 2048
static constexpr int OFF_RMF  = 105472;    // 256
static constexpr int OFF_FLAG = 105728;    // 256
static constexpr int OFF_CNT  = 105984;    // 16
static constexpr int OFF_LIST = 106000;    // 2048
static constexpr int S1_SMEM  = OFF_LIST + LIST_CAP * 4;   // 108048

__global__ __launch_bounds__(512, 2) void s1mma_kernel(const float* __restrict__ x,
                                                       const float* __restrict__ W1,
                                                       const float* __restrict__ b1) {
    extern __shared__ char sm[];
    const int tid  = threadIdx.x;
    const int lane = tid & 31;
    const int wid  = tid >> 5;
    const int wr   = wid >> 3;      // 0..1 (32 rows each)
    const int wc   = wid & 7;       // 0..7 (32 cols each)
    const int seg  = blockIdx.y;

    float* bs  = (float*)(sm + OFF_BS);
    unsigned long long (*rkey)[8] = (unsigned long long(*)[8])(sm + OFF_RKEY);
    float (*rv2)[8] = (float(*)[8])(sm + OFF_RV2);
    float* rmf = (float*)(sm + OFF_RMF);
    int* flag  = (int*)(sm + OFF_FLAG);
    int* cnt   = (int*)(sm + OFF_CNT);
    uint32_t* list = (uint32_t*)(sm + OFF_LIST);

    const uint32_t sBase = smem_u32(sm);
    const uint32_t sB = sBase + OFF_B;
    const uint32_t sA = sBase + OFF_A;

    if (tid < 256) bs[tid] = b1[seg * 256 + tid];

    // B tile: 256x128 bf16, loaded once (4096 uint4, 8 per thread)
    const uint4* wb4 = (const uint4*)g_w1b + (size_t)seg * 256 * 16;
    #pragma unroll
    for (int i = 0; i < 8; i++) {
        int qq = tid + i * 512;
        int r = qq >> 4, c = qq & 15;
        *(uint4*)(sm + OFF_B + r * 256 + ((c ^ (r & 7)) << 4)) = wb4[r * 16 + c];
    }

    // prefetch first A tile into buf 0 (1024 uint4, 2 per thread)
    {
        const uint4* src = (const uint4*)g_xb + (size_t)blockIdx.x * 64 * 16;
        #pragma unroll
        for (int i = 0; i < 2; i++) {
            int qq = tid + i * 512;
            int r = qq >> 4, c = qq & 15;
            cpasync16(sA + r * 256 + ((c ^ (r & 7)) << 4), src + r * 16 + c);
        }
    }
    CP_COMMIT();

    const int q  = lane >> 2;
    const int qt = lane & 3;

    int it = 0;
    for (int t = blockIdx.x; t < NTILE; t += SGRID, it++) {
        int tn = t + SGRID;
        if (tn < NTILE) {
            uint32_t dbuf = sA + ((it + 1) & 1) * 16384;
            const uint4* src = (const uint4*)g_xb + (size_t)tn * 64 * 16;
            #pragma unroll
            for (int i = 0; i < 2; i++) {
                int qq = tid + i * 512;
                int r = qq >> 4, c = qq & 15;
                cpasync16(dbuf + r * 256 + ((c ^ (r & 7)) << 4), src + r * 16 + c);
            }
        }
        CP_COMMIT();
        CP_WAIT1();
        __syncthreads();                               // sync0

        const uint32_t sAc = sA + (it & 1) * 16384;

        float acc[2][4][4];
        #pragma unroll
        for (int mt = 0; mt < 2; mt++)
            #pragma unroll
            for (int nt = 0; nt < 4; nt++)
                #pragma unroll
                for (int e = 0; e < 4; e++) acc[mt][nt][e] = 0.f;

        #pragma unroll
        for (int ks = 0; ks < 8; ks++) {
            uint32_t a[2][4], b[2][4];
            #pragma unroll
            for (int mt = 0; mt < 2; mt++) {
                int r = wr * 32 + mt * 16 + (lane & 15);
                int c = ks * 2 + (lane >> 4);
                ldsm_x4(a[mt], sAc + r * 256 + ((uint32_t)(c ^ (r & 7)) << 4));
            }
            #pragma unroll
            for (int g = 0; g < 2; g++) {
                int r = wc * 32 + g * 16 + (lane & 7) + ((lane >> 4) << 3);
                int c = ks * 2 + ((lane >> 3) & 1);
                ldsm_x4(b[g], sB + r * 256 + ((uint32_t)(c ^ (r & 7)) << 4));
            }
            #pragma unroll
            for (int mt = 0; mt < 2; mt++)
                #pragma unroll
                for (int n8 = 0; n8 < 4; n8++)
                    mma_bf16(acc[mt][n8], a[mt], b[n8 >> 1][(n8 & 1) * 2],
                             b[n8 >> 1][(n8 & 1) * 2 + 1]);
        }

        // bias pre-add (once)
        #pragma unroll
        for (int nt = 0; nt < 4; nt++) {
            float b0v = bs[wc * 32 + nt * 8 + qt * 2];
            float b1v = bs[wc * 32 + nt * 8 + qt * 2 + 1];
            #pragma unroll
            for (int mt = 0; mt < 2; mt++) {
                acc[mt][nt][0] += b0v; acc[mt][nt][1] += b1v;
                acc[mt][nt][2] += b0v; acc[mt][nt][3] += b1v;
            }
        }

        // register top-2 per row per octant (8 positions/thread)
        #pragma unroll
        for (int mt = 0; mt < 2; mt++)
            #pragma unroll
            for (int h = 0; h < 2; h++) {
                float v1 = -FLT_MAX, v2 = -FLT_MAX;
                int i1 = 0;
                #pragma unroll
                for (int j = 0; j < 8; j++) {
                    int nt = j >> 1, c2 = j & 1;
                    int cs = wc * 32 + nt * 8 + qt * 2 + c2;
                    float v = acc[mt][nt][h * 2 + c2];
                    if (v > v1) { v2 = v1; v1 = v; i1 = cs; }
                    else        { v2 = fmaxf(v2, v); }
                }
                #pragma unroll
                for (int off = 1; off <= 2; off <<= 1) {
                    float ov1 = __shfl_xor_sync(0xffffffffu, v1, off);
                    int   oi1 = __shfl_xor_sync(0xffffffffu, i1, off);
                    float ov2 = __shfl_xor_sync(0xffffffffu, v2, off);
                    bool owin = (ov1 > v1) || (ov1 == v1 && oi1 < i1);
                    if (owin) { v2 = fmaxf(v1, ov2); v1 = ov1; i1 = oi1; }
                    else      { v2 = fmaxf(v2, ov1); }
                }
                if (qt == 0) {
                    int rl = wr * 32 + mt * 16 + h * 8 + q;
                    rkey[rl][wc] =
                        ((unsigned long long)ford(v1) << 32) | (uint32_t)(255 - i1);
                    rv2[rl][wc] = v2;
                }
            }
        __syncthreads();                               // sync1

        // merge 8 octants, classify, direct-write unambiguous
        if (tid < 64) {
            unsigned long long K = rkey[tid][0];
            #pragma unroll
            for (int q2 = 1; q2 < 8; q2++) {
                unsigned long long kq = rkey[tid][q2];
                if (kq > K) K = kq;
            }
            float v1 = iford((uint32_t)(K >> 32));
            float s2 = -FLT_MAX;
            #pragma unroll
            for (int q2 = 0; q2 < 8; q2++) {
                unsigned long long kq = rkey[tid][q2];
                float cv = (kq == K) ? rv2[tid][q2] : iford((uint32_t)(kq >> 32));
                s2 = fmaxf(s2, cv);
            }
            int fl = (v1 - s2 <= TAU) ? 1 : 0;
            flag[tid] = fl;
            size_t pair = (size_t)(t * 64 + tid) * NSEG + seg;
            if (!fl) {
                g_idx[pair] = 255 - (int)(K & 0xFFu);
            } else {
                rmf[tid] = v1;
                g_kb[pair] = 0ull;
            }
        }
        if (tid == 0) *cnt = 0;
        __syncthreads();                               // sync2

        // candidate collection (ambiguous rows only) into smem list
        #pragma unroll
        for (int mt = 0; mt < 2; mt++)
            #pragma unroll
            for (int h = 0; h < 2; h++) {
                int rl = wr * 32 + mt * 16 + h * 8 + q;
                if (flag[rl]) {
                    float thr = rmf[rl] - TAU;
                    uint32_t ebase = ((uint32_t)(t * 64 + rl) << 12) | ((uint32_t)seg << 8);
                    #pragma unroll
                    for (int nt = 0; nt < 4; nt++)
                        #pragma unroll
                        for (int c2 = 0; c2 < 2; c2++) {
                            int cs = wc * 32 + nt * 8 + qt * 2 + c2;
                            float v = acc[mt][nt][h * 2 + c2];
                            if (v >= thr) {
                                int p = atomicAdd(cnt, 1);
                                if (p < LIST_CAP) list[p] = ebase | (uint32_t)cs;
                            }
                        }
                }
            }
        __syncthreads();                               // sync3

        // flush list to global queue (single thread; ~25 entries)
        if (tid == 0) {
            int n = *cnt;
            if (n > LIST_CAP) n = LIST_CAP;
            if (n > 0) {
                int base = atomicAdd(&g_qcnt, n);
                for (int i = 0; i < n && base + i < QCAP; i++)
                    g_q[base + i] = list[i];
            }
        }
    }
}

// ------------------------- rescore + finalize -------------------------------
__global__ __launch_bounds__(256) void rescore_kernel(const float* __restrict__ x,
                                                      const float* __restrict__ W1,
                                                      const float* __restrict__ b1) {
    const int lane = threadIdx.x & 31;
    const int gw = (blockIdx.x * 256 + threadIdx.x) >> 5;
    const int nw = gridDim.x * 8;
    int n = g_qcnt;
    if (n > QCAP) n = QCAP;
    for (int i = gw; i < n; i += nw) {
        uint32_t e = g_q[i];
        int row = e >> 12, seg = (e >> 8) & 15, col = e & 255;
        const float4* xr = (const float4*)(x  + (size_t)row * 128);
        const float4* wv = (const float4*)(W1 + (size_t)(seg * 256 + col) * 128);
        float4 xa = __ldg(&xr[lane]);
        float4 wa = __ldg(&wv[lane]);
        float s = xa.x * wa.x + xa.y * wa.y + xa.z * wa.z + xa.w * wa.w;
        #pragma unroll
        for (int off = 16; off > 0; off >>= 1)
            s += __shfl_xor_sync(0xffffffffu, s, off);
        if (lane == 0) {
            float val = s + __ldg(&b1[seg * 256 + col]);
            unsigned long long key =
                ((unsigned long long)ford(val) << 32) | (uint32_t)(255 - col);
            atomicMax(&g_kb[(size_t)row * NSEG + seg], key);
        }
    }
}

__global__ __launch_bounds__(256) void finalize_kernel() {
    int n = g_qcnt;
    if (n > QCAP) n = QCAP;
    for (int i = blockIdx.x * 256 + threadIdx.x; i < n; i += gridDim.x * 256) {
        uint32_t e = g_q[i];
        size_t pair = (size_t)(e >> 12) * NSEG + ((e >> 8) & 15);
        g_idx[pair] = 255 - (int)(g_kb[pair] & 0xFFu);
    }
}

// --------------------------------- gather ---------------------------------
__global__ __launch_bounds__(128) void gather_kernel(float* __restrict__ out) {
    const int rowbase = blockIdx.x * 16;
    const int t = threadIdx.x;
    __shared__ int sidx[16][16];
    #pragma unroll
    for (int qq = t; qq < 256; qq += 128)
        sidx[qq >> 4][qq & 15] = g_idx[(size_t)(rowbase + (qq >> 4)) * NSEG + (qq & 15)];
    __syncthreads();

    const float cv = g_c[t];
    float acc[16];
    #pragma unroll
    for (int r = 0; r < 16; r++) acc[r] = cv;

    #pragma unroll
    for (int s = 0; s < NSEG; s++) {
        #pragma unroll
        for (int r = 0; r < 16; r++) {
            int col = (s << 8) + sidx[r][s];
            acc[r] += g_MT[(size_t)col * D + t];
        }
    }
    #pragma unroll
    for (int r = 0; r < 16; r++)
        out[(size_t)(rowbase + r) * D + t] = acc[r];
}

// ------------------------------- launcher ----------------------------------
extern "C" void kernel_launch(void* const* d_in, const int* in_sizes, int n_in,
                              void* d_out, int out_size) {
    const float* x  = (const float*)d_in[0];
    const float* W1 = (const float*)d_in[1];
    const float* b1 = (const float*)d_in[2];
    const float* W2 = (const float*)d_in[3];
    const float* b2 = (const float*)d_in[4];
    const float* W3 = (const float*)d_in[5];
    const float* b3 = (const float*)d_in[6];
    float* out = (float*)d_out;
    const int B = in_sizes[0] / D;   // 32768

    void *p_xb = nullptr, *p_w1b = nullptr, *p_qcnt = nullptr;
    cudaGetSymbolAddress(&p_xb,  g_xb);
    cudaGetSymbolAddress(&p_w1b, g_w1b);
    cudaGetSymbolAddress(&p_qcnt, g_qcnt);

    cudaFuncSetAttribute(s1mma_kernel,
                         cudaFuncAttributeMaxDynamicSharedMemorySize, S1_SMEM);
    cudaFuncSetAttribute(mm2_kernel,
                         cudaFuncAttributeMaxDynamicSharedMemorySize, MM_SMEM);

    static cudaStream_t s2 = nullptr;
    static cudaEvent_t evF = nullptr, evJ = nullptr;
    if (s2 == nullptr) {
        cudaStreamCreateWithFlags(&s2, cudaStreamNonBlocking);
        cudaEventCreateWithFlags(&evF, cudaEventDisableTiming);
        cudaEventCreateWithFlags(&evJ, cudaEventDisableTiming);
    }

    cudaMemsetAsync(p_qcnt, 0, sizeof(int));

    // fork the weight-only M-path onto s2
    cudaEventRecord(evF, 0);
    cudaStreamWaitEvent(s2, evF, 0);
    w3split_kernel<<<(H * D / 2 + 255) / 256, 256, 0, s2>>>(W3);
    w2split_kernel<<<dim3(H / 64, H / 64), 256, 0, s2>>>(W2);
    c_kernel<<<16, 256, 0, s2>>>(W3, b2, b3);
    mm2_kernel<<<dim3(32, 8), 256, MM_SMEM, s2>>>();
    mreduce_kernel<<<(H * D / 4 + 255) / 256, 256, 0, s2>>>();
    cudaEventRecord(evJ, s2);

    // main chain: x/W1 bf16 convert -> s1 -> rescore -> finalize
    convertb_kernel<<<(B * D / 8 + 255) / 256, 256>>>(x,  (__nv_bfloat16*)p_xb,  B * D / 8);
    convertb_kernel<<<(H * D / 8 + 255) / 256, 256>>>(W1, (__nv_bfloat16*)p_w1b, H * D / 8);
    s1mma_kernel<<<dim3(SGRID, NSEG), 512, S1_SMEM>>>(x, W1, b1);
    rescore_kernel<<<2048, 256>>>(x, W1, b1);
    finalize_kernel<<<512, 256>>>();

    // join M-path, then gather
    cudaStreamWaitEvent(0, evJ, 0);
    gather_kernel<<<B / 16, 128>>>(out);
}